// round 5
// baseline (speedup 1.0000x reference)
#include <cuda_runtime.h>
#include <cuda_fp16.h>

#define Bq 512
#define Tq 128
#define Eq 256
#define Dq 256
#define G4 1024
#define BT (Bq*Tq)
#define NBLK 512
#define NLEAF 16
#define PER_LEAF (NBLK/NLEAF)

// ---------------- static device scratch ----------------
__device__ __half g_pre[(size_t)BT * Eq];     // enc @ W1_enc + b1 (fp16, 32MB)
__device__ __half g_encH[(size_t)BT * Eq];    // fp16 copy of enc (32MB)
__device__ float g_bsum[G4];                  // b_ih + b_hh
__device__ float g_h[Bq * Dq];
__device__ float g_c[Bq * Dq];
__device__ float g_hp[16 * Bq * Eq];          // 16 K-partials of [h|c]@W1_hc
__device__ float g_gp[8 * (size_t)Bq * G4];   // 8 K-partials of h@w_hhT
// pre-split tf32 weights (hi/lo)
__device__ float g_whhT_hi[Dq * G4];          // [k][gate*256+d]
__device__ float g_whhT_lo[Dq * G4];
__device__ float g_w1hc_hi[512 * Eq];         // attn_w1 rows 0..511
__device__ float g_w1hc_lo[512 * Eq];
__device__ float g_w1e_hi[Eq * Eq];           // attn_w1 rows 512..767
__device__ float g_w1e_lo[Eq * Eq];
__device__ unsigned g_cnt[NLEAF * 32];
__device__ unsigned g_master;
__device__ volatile unsigned g_gen;

struct SmA { float2 As2[16][137]; float2 Bs2[16][73]; };
struct SmB {
    float hp[256]; float sc[128]; float ctxp[8][256];
    float ctx[256]; float red[8]; float misc[4];
};
union Smem { SmA a; SmB b; };

__device__ __forceinline__ float tanh_approx(float x) {
    float y; asm("tanh.approx.f32 %0, %1;" : "=f"(y) : "f"(x)); return y;
}
__device__ __forceinline__ float sigmoid_f(float x) {
    return __fdividef(1.0f, 1.0f + __expf(-x));
}
__device__ __forceinline__ unsigned f2tf32(float x) {
    unsigned r; asm("cvt.rna.tf32.f32 %0, %1;" : "=r"(r) : "f"(x)); return r;
}
__device__ __forceinline__ float2 split_tf32(float x) {
    float hi = __uint_as_float(f2tf32(x));
    float lo = __uint_as_float(f2tf32(x - hi));
    return make_float2(hi, lo);
}
__device__ __forceinline__ void mma_tf32(float c[4],
        unsigned a0, unsigned a1, unsigned a2, unsigned a3,
        unsigned b0, unsigned b1)
{
    asm volatile(
        "mma.sync.aligned.m16n8k8.row.col.f32.tf32.tf32.f32 "
        "{%0,%1,%2,%3},{%4,%5,%6,%7},{%8,%9},{%0,%1,%2,%3};"
        : "+f"(c[0]), "+f"(c[1]), "+f"(c[2]), "+f"(c[3])
        : "r"(a0), "r"(a1), "r"(a2), "r"(a3), "r"(b0), "r"(b1));
}

// 128x64 tile GEMM on tensor cores, tf32 3-term split (~fp32 precision).
// A: fp32 [128 x K] (lda), split during staging.
// Bhi/Blo: pre-split tf32 [K x 64-slice] (ldb).
template<typename TO>
__device__ __forceinline__ void mma_gemm128x64(SmA* s,
        const float* __restrict__ A, int lda,
        const float* __restrict__ Bhi, const float* __restrict__ Blo, int ldb,
        TO* __restrict__ C, int ldc, int K, const float* __restrict__ bias)
{
    const int tid = threadIdx.x;
    const int lane = tid & 31, warp = tid >> 5;
    const int wm = warp >> 1, wn = warp & 1;
    const int g = lane >> 2, tg = lane & 3;

    float acc[2][4][4];
#pragma unroll
    for (int mi = 0; mi < 2; mi++)
#pragma unroll
        for (int ni = 0; ni < 4; ni++)
#pragma unroll
            for (int j = 0; j < 4; j++) acc[mi][ni][j] = 0.f;

    const int arow = tid >> 1, acb = (tid & 1) * 8;
    const int bk = tid >> 4, bn = (tid & 15) * 4;

    for (int k0 = 0; k0 < K; k0 += 16) {
        // stage A (split to tf32 hi/lo)
        {
            const float* ap = A + (size_t)arow * lda + k0 + acb;
            float4 v0 = __ldcg((const float4*)ap);
            float4 v1 = __ldcg((const float4*)(ap + 4));
            float vv[8] = {v0.x, v0.y, v0.z, v0.w, v1.x, v1.y, v1.z, v1.w};
#pragma unroll
            for (int j = 0; j < 8; j++)
                s->As2[acb + j][arow] = split_tf32(vv[j]);
        }
        // stage B (pre-split)
        {
            float4 hv = __ldcg((const float4*)(Bhi + (size_t)(k0 + bk) * ldb + bn));
            float4 lv = __ldcg((const float4*)(Blo + (size_t)(k0 + bk) * ldb + bn));
            s->Bs2[bk][bn + 0] = make_float2(hv.x, lv.x);
            s->Bs2[bk][bn + 1] = make_float2(hv.y, lv.y);
            s->Bs2[bk][bn + 2] = make_float2(hv.z, lv.z);
            s->Bs2[bk][bn + 3] = make_float2(hv.w, lv.w);
        }
        __syncthreads();

#pragma unroll
        for (int ks = 0; ks < 2; ks++) {
            const int kk = ks * 8;
#pragma unroll
            for (int mi = 0; mi < 2; mi++) {
                const int m0 = wm * 32 + mi * 16;
                float2 p0 = s->As2[kk + tg][m0 + g];
                float2 p1 = s->As2[kk + tg][m0 + g + 8];
                float2 p2 = s->As2[kk + tg + 4][m0 + g];
                float2 p3 = s->As2[kk + tg + 4][m0 + g + 8];
                unsigned ah0 = __float_as_uint(p0.x), al0 = __float_as_uint(p0.y);
                unsigned ah1 = __float_as_uint(p1.x), al1 = __float_as_uint(p1.y);
                unsigned ah2 = __float_as_uint(p2.x), al2 = __float_as_uint(p2.y);
                unsigned ah3 = __float_as_uint(p3.x), al3 = __float_as_uint(p3.y);
#pragma unroll
                for (int ni = 0; ni < 4; ni++) {
                    const int n0 = wn * 32 + ni * 8;
                    float2 q0 = s->Bs2[kk + tg][n0 + g];
                    float2 q1 = s->Bs2[kk + tg + 4][n0 + g];
                    unsigned bh0 = __float_as_uint(q0.x), bl0 = __float_as_uint(q0.y);
                    unsigned bh1 = __float_as_uint(q1.x), bl1 = __float_as_uint(q1.y);
                    mma_tf32(acc[mi][ni], ah0, ah1, ah2, ah3, bh0, bh1);
                    mma_tf32(acc[mi][ni], al0, al1, al2, al3, bh0, bh1);
                    mma_tf32(acc[mi][ni], ah0, ah1, ah2, ah3, bl0, bl1);
                }
            }
        }
        __syncthreads();
    }

    // epilogue
#pragma unroll
    for (int mi = 0; mi < 2; mi++) {
        const int r0 = wm * 32 + mi * 16 + g;
#pragma unroll
        for (int ni = 0; ni < 4; ni++) {
            const int cc = wn * 32 + ni * 8 + 2 * tg;
            float v0 = acc[mi][ni][0], v1 = acc[mi][ni][1];
            float v2 = acc[mi][ni][2], v3 = acc[mi][ni][3];
            if (bias) { v0 += bias[cc]; v1 += bias[cc + 1]; v2 += bias[cc]; v3 += bias[cc + 1]; }
            if constexpr (sizeof(TO) == 2) {
                __half2 h0 = __floats2half2_rn(v0, v1);
                __half2 h1 = __floats2half2_rn(v2, v3);
                *(__half2*)((__half*)C + (size_t)r0 * ldc + cc) = h0;
                *(__half2*)((__half*)C + (size_t)(r0 + 8) * ldc + cc) = h1;
            } else {
                *(float2*)((float*)C + (size_t)r0 * ldc + cc) = make_float2(v0, v1);
                *(float2*)((float*)C + (size_t)(r0 + 8) * ldc + cc) = make_float2(v2, v3);
            }
        }
    }
}

__device__ __forceinline__ void gridbar() {
    __threadfence();
    __syncthreads();
    if (threadIdx.x == 0) {
        unsigned gen = g_gen;
        unsigned leaf = (blockIdx.x & (NLEAF - 1)) * 32;
        unsigned v = atomicAdd(&g_cnt[leaf], 1u) + 1u;
        if (v == (gen + 1u) * PER_LEAF) {
            unsigned m = atomicAdd(&g_master, 1u) + 1u;
            if (m == (gen + 1u) * NLEAF) {
                g_gen = gen + 1u;
            } else {
                while (g_gen == gen) __nanosleep(32);
            }
        } else {
            while (g_gen == gen) __nanosleep(64);
        }
        __threadfence();
    }
    __syncthreads();
}

__global__ void __launch_bounds__(256, 4) decoder_persist(
        const float* __restrict__ yhist,
        const float* __restrict__ attn_w2, const float* __restrict__ w_ih,
        const float* __restrict__ fc_w, const float* __restrict__ fc_b,
        const float* __restrict__ fcf_w, const float* __restrict__ fcf_b,
        float* __restrict__ out)
{
    __shared__ Smem sm;
    const int bid = blockIdx.x;
    const int tid = threadIdx.x;
    const int lane = tid & 31, warp = tid >> 5;
    const int b = bid;

    for (int t = 0; t < Tq; t++) {
        // ============ phase 1: all step-GEMM partials (tensor cores) ============
        {   // gp unit = bid : h @ w_hhT, tile 128x64, K-chunk 32
            int tile = bid >> 3, kq = bid & 7;
            int mt = tile >> 4, nt = tile & 15;
            mma_gemm128x64<float>(&sm.a,
                g_h + (size_t)mt * 128 * Dq + kq * 32, Dq,
                g_whhT_hi + (size_t)(kq * 32) * G4 + nt * 64,
                g_whhT_lo + (size_t)(kq * 32) * G4 + nt * 64, G4,
                g_gp + (size_t)kq * (Bq * G4) + (size_t)mt * 128 * G4 + nt * 64, G4,
                32, (const float*)0);
        }
        if ((bid & 1) == 0) {   // hp unit = bid>>1 : [h|c] @ W1_hc
            int u = bid >> 1;
            int tile = u >> 4, kq = u & 15;
            int mt = tile >> 2, nt = tile & 3;
            const float* A = (kq < 8 ? g_h + kq * 32 : g_c + (kq - 8) * 32)
                             + (size_t)mt * 128 * Dq;
            mma_gemm128x64<float>(&sm.a, A, Dq,
                g_w1hc_hi + (size_t)(kq * 32) * Eq + nt * 64,
                g_w1hc_lo + (size_t)(kq * 32) * Eq + nt * 64, Eq,
                g_hp + (size_t)kq * (Bq * Eq) + (size_t)mt * 128 * Eq + nt * 64, Eq,
                32, (const float*)0);
        }
        gridbar();

        // ============ phase 2: attention + LSTM, all row-local (row b = bid) ============
        {
            float hpv = 0.f;
#pragma unroll
            for (int q = 0; q < 16; q++)
                hpv += __ldcg(&g_hp[(size_t)q * (Bq * Eq) + b * Eq + tid]);
            sm.b.hp[tid] = hpv;
            __syncthreads();

            float hpr[8], w2r[8];
#pragma unroll
            for (int j = 0; j < 8; j++) {
                hpr[j] = sm.b.hp[lane * 8 + j];
                w2r[j] = attn_w2[lane * 8 + j];
            }

            // scores: warp handles 16 t's, 4 loads in flight
            const uint4* preb = (const uint4*)(g_pre + (size_t)b * Tq * Eq);
#pragma unroll
            for (int tb = 0; tb < 4; tb++) {
                int tt0 = warp + tb * 32;
                uint4 pv[4];
#pragma unroll
                for (int j = 0; j < 4; j++)
                    pv[j] = __ldcg(preb + (size_t)(tt0 + j * 8) * 32 + lane);
#pragma unroll
                for (int j = 0; j < 4; j++) {
                    const __half2* ph = (const __half2*)&pv[j];
                    float a = 0.f;
#pragma unroll
                    for (int q = 0; q < 4; q++) {
                        float2 f = __half22float2(ph[q]);
                        a = fmaf(w2r[2 * q],     tanh_approx(hpr[2 * q]     + f.x), a);
                        a = fmaf(w2r[2 * q + 1], tanh_approx(hpr[2 * q + 1] + f.y), a);
                    }
#pragma unroll
                    for (int o = 16; o; o >>= 1) a += __shfl_xor_sync(0xffffffffu, a, o);
                    if (lane == 0) sm.b.sc[tt0 + j * 8] = a;
                }
            }
            __syncthreads();

            // softmax over T=128 (attn_b2 dropped: shift-invariant)
            float sv = (tid < Tq) ? sm.b.sc[tid] : -3.0e38f;
            float m = sv;
#pragma unroll
            for (int o = 16; o; o >>= 1) m = fmaxf(m, __shfl_xor_sync(0xffffffffu, m, o));
            if (lane == 0) sm.b.red[warp] = m;
            __syncthreads();
            if (tid == 0) {
                float mm = sm.b.red[0];
#pragma unroll
                for (int w = 1; w < 8; w++) mm = fmaxf(mm, sm.b.red[w]);
                sm.b.misc[0] = mm;
            }
            __syncthreads();
            float ex = (tid < Tq) ? __expf(sv - sm.b.misc[0]) : 0.f;
            float ss = ex;
#pragma unroll
            for (int o = 16; o; o >>= 1) ss += __shfl_xor_sync(0xffffffffu, ss, o);
            if (lane == 0) sm.b.red[warp] = ss;
            __syncthreads();
            if (tid == 0) {
                float tot = 0.f;
#pragma unroll
                for (int w = 0; w < 8; w++) tot += sm.b.red[w];
                sm.b.misc[1] = __fdividef(1.0f, tot);
            }
            if (tid < Tq) sm.b.sc[tid] = ex;
            __syncthreads();
            float invs = sm.b.misc[1];

            // ctx: warp w accumulates 16 t's over all 256 e (8 per lane), fp16 enc
            float a8[8] = {0.f, 0.f, 0.f, 0.f, 0.f, 0.f, 0.f, 0.f};
            const uint4* encb = (const uint4*)(g_encH + (size_t)b * Tq * Eq);
#pragma unroll 4
            for (int i = 0; i < 16; i++) {
                int tt = (warp << 4) + i;
                float wgt = sm.b.sc[tt];
                uint4 ev = __ldcg(encb + (size_t)tt * 32 + lane);
                const __half2* eh = (const __half2*)&ev;
#pragma unroll
                for (int q = 0; q < 4; q++) {
                    float2 f = __half22float2(eh[q]);
                    a8[2 * q]     = fmaf(wgt, f.x, a8[2 * q]);
                    a8[2 * q + 1] = fmaf(wgt, f.y, a8[2 * q + 1]);
                }
            }
#pragma unroll
            for (int j = 0; j < 8; j++) sm.b.ctxp[warp][lane * 8 + j] = a8[j];
            __syncthreads();
            float cv = 0.f;
#pragma unroll
            for (int w = 0; w < 8; w++) cv += sm.b.ctxp[w][tid];
            cv *= invs;
            sm.b.ctx[tid] = cv;

            // y_tilde = ctx . fc_w[0:256] + y_t*fc_w[256] + fc_b
            float ps = cv * fc_w[tid];
#pragma unroll
            for (int o = 16; o; o >>= 1) ps += __shfl_xor_sync(0xffffffffu, ps, o);
            __syncthreads();
            if (lane == 0) sm.b.red[warp] = ps;
            __syncthreads();
            if (tid == 0) {
                float tot = 0.f;
#pragma unroll
                for (int w = 0; w < 8; w++) tot += sm.b.red[w];
                sm.b.misc[2] = tot + yhist[b * Tq + t] * fc_w[256] + fc_b[0];
            }
            __syncthreads();

            // LSTM epilogue (thread = d)
            float yt = sm.b.misc[2];
            int d = tid;
            float gv[4];
#pragma unroll
            for (int g = 0; g < 4; g++) {
                float a = fmaf(yt, w_ih[g * 256 + d], g_bsum[g * 256 + d]);
#pragma unroll
                for (int kq = 0; kq < 8; kq++)
                    a += __ldcg(&g_gp[(size_t)kq * (Bq * G4) + (size_t)b * G4 + g * 256 + d]);
                gv[g] = a;
            }
            float cprev = g_c[b * Dq + d];
            float cn = sigmoid_f(gv[1]) * cprev + sigmoid_f(gv[0]) * tanhf(gv[2]);
            float hn = sigmoid_f(gv[3]) * tanhf(cn);
            g_c[b * Dq + d] = cn;
            g_h[b * Dq + d] = hn;

            if (t == Tq - 1) {
                float q = hn * fcf_w[d] + sm.b.ctx[d] * fcf_w[Dq + d];
#pragma unroll
                for (int o = 16; o; o >>= 1) q += __shfl_xor_sync(0xffffffffu, q, o);
                __syncthreads();
                if (lane == 0) sm.b.red[warp] = q;
                __syncthreads();
                if (tid == 0) {
                    float tot = 0.f;
#pragma unroll
                    for (int w = 0; w < 8; w++) tot += sm.b.red[w];
                    out[b] = tot + fcf_b[0];
                }
            }
        }
        gridbar();
    }
}

__global__ void prep_kernel(const float* __restrict__ w_hh,
                            const float* __restrict__ b_ih,
                            const float* __restrict__ b_hh,
                            const float* __restrict__ enc,
                            const float* __restrict__ attn_w1)
{
    int i = blockIdx.x * blockDim.x + threadIdx.x;   // 262144 threads
    if (i < G4 * Dq) {           // transpose + split w_hh
        int j = i >> 8, k = i & 255;
        float2 s = split_tf32(w_hh[i]);
        g_whhT_hi[(size_t)k * G4 + j] = s.x;
        g_whhT_lo[(size_t)k * G4 + j] = s.y;
    }
    if (i < 512 * Eq) {          // split attn_w1 h|c block
        float2 s = split_tf32(attn_w1[i]);
        g_w1hc_hi[i] = s.x; g_w1hc_lo[i] = s.y;
    }
    if (i < Eq * Eq) {           // split attn_w1 enc block
        float2 s = split_tf32(attn_w1[512 * Eq + i]);
        g_w1e_hi[i] = s.x; g_w1e_lo[i] = s.y;
    }
    if (i < G4) g_bsum[i] = b_ih[i] + b_hh[i];
    if (i < Bq * Dq) { g_h[i] = 0.f; g_c[i] = 0.f; }
    if (i < NLEAF * 32) g_cnt[i] = 0u;
    if (i == 0) { g_master = 0u; g_gen = 0u; }
    for (size_t j = i; j < (size_t)BT * Eq; j += 262144)
        g_encH[j] = __float2half(enc[j]);
}

__global__ void __launch_bounds__(256) pre_gemm_kernel(
        const float* __restrict__ enc, const float* __restrict__ attn_b1)
{
    __shared__ SmA sa;
    int mt = blockIdx.x >> 2, nt = blockIdx.x & 3;   // 512 row-tiles x 4 col-tiles
    mma_gemm128x64<__half>(&sa,
        enc + (size_t)mt * 128 * Eq, Eq,
        g_w1e_hi + nt * 64, g_w1e_lo + nt * 64, Eq,
        g_pre + (size_t)mt * 128 * Eq + nt * 64, Eq, 256,
        attn_b1 + nt * 64);
}

extern "C" void kernel_launch(void* const* d_in, const int* in_sizes, int n_in,
                              void* d_out, int out_size)
{
    const float* enc     = (const float*)d_in[0];
    const float* yhist   = (const float*)d_in[1];
    const float* attn_w1 = (const float*)d_in[2];
    const float* attn_b1 = (const float*)d_in[3];
    const float* attn_w2 = (const float*)d_in[4];
    // d_in[5] = attn_b2: unused (softmax is shift-invariant)
    const float* w_ih    = (const float*)d_in[6];
    const float* w_hh    = (const float*)d_in[7];
    const float* b_ih    = (const float*)d_in[8];
    const float* b_hh    = (const float*)d_in[9];
    const float* fc_w    = (const float*)d_in[10];
    const float* fc_b    = (const float*)d_in[11];
    const float* fcf_w   = (const float*)d_in[12];
    const float* fcf_b   = (const float*)d_in[13];
    float* out = (float*)d_out;

    prep_kernel<<<1024, 256>>>(w_hh, b_ih, b_hh, enc, attn_w1);
    pre_gemm_kernel<<<2048, 256>>>(enc, attn_b1);
    decoder_persist<<<NBLK, 256>>>(yhist, attn_w2, w_ih,
                                   fc_w, fc_b, fcf_w, fcf_b, out);
}

// round 6
// speedup vs baseline: 1.7283x; 1.7283x over previous
#include <cuda_runtime.h>
#include <cuda_fp16.h>

#define Bq 512
#define Tq 128
#define Eq 256
#define Dq 256
#define G4 1024
#define BT (Bq*Tq)
#define NBLK 512
#define NLEAF 16
#define PER_LEAF (NBLK/NLEAF)

// ---------------- static device scratch ----------------
__device__ __half g_pre[(size_t)BT * Eq];     // enc @ W1_enc + b1 (fp16, 32MB)
__device__ float g_encfc[BT];                 // enc[b,t,:] . fc_w[0:256]  (256KB)
__device__ float g_whhT[Dq * G4];             // w_hh transposed [k][gate*256+d]
__device__ float g_bsum[G4];                  // b_ih + b_hh
__device__ float g_h[Bq * Dq];
__device__ float g_c[Bq * Dq];
__device__ float g_hp[16 * Bq * Eq];          // 16 K-partials of [h|c]@W1_hc
__device__ float g_gp[4 * (size_t)Bq * G4];   // 4 K-partials of h@w_hhT
__device__ unsigned g_cnt[NLEAF * 32];        // leaf counters (spread 128B apart)
__device__ unsigned g_master;
__device__ volatile unsigned g_gen;

struct SmA { float As[16][136]; float Bs[16][68]; };
struct SmB {
    float hp[256]; float sc[128]; float ctxp[8][256];
    float ctx[256]; float red[8]; float misc[4];
};
union Smem { SmA a; SmB b; };

__device__ __forceinline__ float tanh_approx(float x) {
    float y; asm("tanh.approx.f32 %0, %1;" : "=f"(y) : "f"(x)); return y;
}
__device__ __forceinline__ float sigmoid_f(float x) {
    return __fdividef(1.0f, 1.0f + __expf(-x));
}

// 128x64 output tile, K multiple of 16, 256 threads, 8x4 microtile. (R4 engine)
template<typename TO>
__device__ __forceinline__ void gemm128x64(SmA* s,
        const float* __restrict__ A, int lda,
        const float* __restrict__ Bm, int ldb,
        TO* __restrict__ C, int ldc, int K,
        const float* __restrict__ bias)
{
    const int tid = threadIdx.x;
    const int ty = tid >> 4, tx = tid & 15;
    const int arow = tid >> 2, ac4 = (tid & 3) << 2;
    const int bk = tid >> 4, bc4 = (tid & 15) << 2;

    float acc[8][4];
#pragma unroll
    for (int i = 0; i < 8; i++)
#pragma unroll
        for (int j = 0; j < 4; j++) acc[i][j] = 0.f;

    for (int k0 = 0; k0 < K; k0 += 16) {
        float4 av0 = __ldcg((const float4*)(A + (size_t)arow * lda + k0 + ac4));
        float4 av1 = __ldcg((const float4*)(A + (size_t)(arow + 64) * lda + k0 + ac4));
        float4 bv  = __ldcg((const float4*)(Bm + (size_t)(k0 + bk) * ldb + bc4));
        s->As[ac4 + 0][arow] = av0.x; s->As[ac4 + 1][arow] = av0.y;
        s->As[ac4 + 2][arow] = av0.z; s->As[ac4 + 3][arow] = av0.w;
        s->As[ac4 + 0][arow + 64] = av1.x; s->As[ac4 + 1][arow + 64] = av1.y;
        s->As[ac4 + 2][arow + 64] = av1.z; s->As[ac4 + 3][arow + 64] = av1.w;
        *(float4*)&s->Bs[bk][bc4] = bv;
        __syncthreads();
#pragma unroll
        for (int k = 0; k < 16; k++) {
            float4 a0 = *(const float4*)&s->As[k][ty << 3];
            float4 a1 = *(const float4*)&s->As[k][(ty << 3) + 4];
            float4 b4 = *(const float4*)&s->Bs[k][tx << 2];
            float av[8] = {a0.x, a0.y, a0.z, a0.w, a1.x, a1.y, a1.z, a1.w};
            float bb[4] = {b4.x, b4.y, b4.z, b4.w};
#pragma unroll
            for (int i = 0; i < 8; i++)
#pragma unroll
                for (int j = 0; j < 4; j++)
                    acc[i][j] = fmaf(av[i], bb[j], acc[i][j]);
        }
        __syncthreads();
    }
#pragma unroll
    for (int i = 0; i < 8; i++) {
        float v0 = acc[i][0], v1 = acc[i][1], v2 = acc[i][2], v3 = acc[i][3];
        if (bias) {
            v0 += bias[(tx << 2) + 0]; v1 += bias[(tx << 2) + 1];
            v2 += bias[(tx << 2) + 2]; v3 += bias[(tx << 2) + 3];
        }
        size_t off = (size_t)((ty << 3) + i) * ldc + (tx << 2);
        if constexpr (sizeof(TO) == 2) {
            __half2 h0 = __floats2half2_rn(v0, v1);
            __half2 h1 = __floats2half2_rn(v2, v3);
            uint2 u; u.x = *(unsigned*)&h0; u.y = *(unsigned*)&h1;
            *(uint2*)((__half*)C + off) = u;
        } else {
            *(float4*)((float*)C + off) = make_float4(v0, v1, v2, v3);
        }
    }
}

__device__ __forceinline__ void gridbar() {
    __threadfence();
    __syncthreads();
    if (threadIdx.x == 0) {
        unsigned gen = g_gen;
        unsigned leaf = (blockIdx.x & (NLEAF - 1)) * 32;
        unsigned v = atomicAdd(&g_cnt[leaf], 1u) + 1u;
        if (v == (gen + 1u) * PER_LEAF) {
            unsigned m = atomicAdd(&g_master, 1u) + 1u;
            if (m == (gen + 1u) * NLEAF) {
                g_gen = gen + 1u;
            } else {
                while (g_gen == gen) __nanosleep(32);
            }
        } else {
            while (g_gen == gen) __nanosleep(64);
        }
        __threadfence();
    }
    __syncthreads();
}

__global__ void __launch_bounds__(256, 4) decoder_persist(
        const float* __restrict__ enc, const float* __restrict__ yhist,
        const float* __restrict__ attn_w1, const float* __restrict__ attn_w2,
        const float* __restrict__ w_ih,
        const float* __restrict__ fc_w, const float* __restrict__ fc_b,
        const float* __restrict__ fcf_w, const float* __restrict__ fcf_b,
        float* __restrict__ out)
{
    __shared__ Smem sm;
    const int bid = blockIdx.x;
    const int tid = threadIdx.x;
    const int lane = tid & 31, warp = tid >> 5;
    const int b = bid;

    for (int t = 0; t < Tq; t++) {
        // ============ phase 1: step-GEMM partials, one unit per block ============
        if (bid < 256) {
            // gp unit: h @ w_hhT, tile 128x64, K-chunk 64 -> 4 partials
            int kq = bid & 3, tile = bid >> 2;
            int mt = tile >> 4, nt = tile & 15;
            gemm128x64<float>(&sm.a,
                g_h + (size_t)mt * 128 * Dq + kq * 64, Dq,
                g_whhT + (size_t)(kq * 64) * G4 + nt * 64, G4,
                g_gp + (size_t)kq * (Bq * G4) + (size_t)mt * 128 * G4 + nt * 64, G4,
                64, (const float*)0);
        } else {
            // hp unit: [h|c] @ W1_hc, tile 128x64, K-chunk 32 -> 16 partials
            int u = bid - 256;
            int tile = u >> 4, kq = u & 15;
            int mt = tile >> 2, nt = tile & 3;
            const float* A = (kq < 8 ? g_h + kq * 32 : g_c + (kq - 8) * 32)
                             + (size_t)mt * 128 * Dq;
            gemm128x64<float>(&sm.a, A, Dq,
                attn_w1 + (size_t)(kq * 32) * Eq + nt * 64, Eq,
                g_hp + (size_t)kq * (Bq * Eq) + (size_t)mt * 128 * Eq + nt * 64, Eq,
                32, (const float*)0);
        }
        gridbar();

        // ============ phase 2: attention + LSTM, all row-local (row b = bid) ============
        {
            float hpv = 0.f;
#pragma unroll
            for (int q = 0; q < 16; q++)
                hpv += __ldcg(&g_hp[(size_t)q * (Bq * Eq) + b * Eq + tid]);
            sm.b.hp[tid] = hpv;
            __syncthreads();

            float hpr[8], w2r[8];
#pragma unroll
            for (int j = 0; j < 8; j++) {
                hpr[j] = sm.b.hp[lane * 8 + j];
                w2r[j] = attn_w2[lane * 8 + j];
            }

            // scores: warp handles 16 t's, 4 loads in flight
            const uint4* preb = (const uint4*)(g_pre + (size_t)b * Tq * Eq);
#pragma unroll
            for (int tb = 0; tb < 4; tb++) {
                int tt0 = warp + tb * 32;
                uint4 pv[4];
#pragma unroll
                for (int j = 0; j < 4; j++)
                    pv[j] = __ldcg(preb + (size_t)(tt0 + j * 8) * 32 + lane);
#pragma unroll
                for (int j = 0; j < 4; j++) {
                    const __half2* ph = (const __half2*)&pv[j];
                    float a = 0.f;
#pragma unroll
                    for (int q = 0; q < 4; q++) {
                        float2 f = __half22float2(ph[q]);
                        a = fmaf(w2r[2 * q],     tanh_approx(hpr[2 * q]     + f.x), a);
                        a = fmaf(w2r[2 * q + 1], tanh_approx(hpr[2 * q + 1] + f.y), a);
                    }
#pragma unroll
                    for (int o = 16; o; o >>= 1) a += __shfl_xor_sync(0xffffffffu, a, o);
                    if (lane == 0) sm.b.sc[tt0 + j * 8] = a;
                }
            }
            __syncthreads();

            // softmax over T=128 (attn_b2 dropped: shift-invariant)
            float sv = (tid < Tq) ? sm.b.sc[tid] : -3.0e38f;
            float m = sv;
#pragma unroll
            for (int o = 16; o; o >>= 1) m = fmaxf(m, __shfl_xor_sync(0xffffffffu, m, o));
            if (lane == 0) sm.b.red[warp] = m;
            __syncthreads();
            if (tid == 0) {
                float mm = sm.b.red[0];
#pragma unroll
                for (int w = 1; w < 8; w++) mm = fmaxf(mm, sm.b.red[w]);
                sm.b.misc[0] = mm;
            }
            __syncthreads();
            float ex = (tid < Tq) ? __expf(sv - sm.b.misc[0]) : 0.f;
            float ss = ex;
#pragma unroll
            for (int o = 16; o; o >>= 1) ss += __shfl_xor_sync(0xffffffffu, ss, o);
            if (lane == 0) sm.b.red[warp] = ss;
            __syncthreads();
            if (tid == 0) {
                float tot = 0.f;
#pragma unroll
                for (int w = 0; w < 8; w++) tot += sm.b.red[w];
                sm.b.misc[1] = __fdividef(1.0f, tot);
            }
            if (tid < Tq) sm.b.sc[tid] = ex;
            __syncthreads();
            float invs = sm.b.misc[1];

            // y_dot = sum_t ex[t] * encfc[b,t]  (replaces full ctx pass)
            float yd = (tid < Tq) ? sm.b.sc[tid] * __ldcg(&g_encfc[b * Tq + tid]) : 0.f;
#pragma unroll
            for (int o = 16; o; o >>= 1) yd += __shfl_xor_sync(0xffffffffu, yd, o);
            if (lane == 0) sm.b.red[warp] = yd;
            __syncthreads();
            if (tid == 0) {
                float tot = 0.f;
#pragma unroll
                for (int w = 0; w < 8; w++) tot += sm.b.red[w];
                sm.b.misc[2] = tot * invs + yhist[b * Tq + t] * fc_w[256] + fc_b[0];
            }

            // full ctx only needed at the final step (for fc_final)
            if (t == Tq - 1) {
                float a8[8] = {0.f, 0.f, 0.f, 0.f, 0.f, 0.f, 0.f, 0.f};
                const float4* encb = (const float4*)(enc + (size_t)b * Tq * Eq);
#pragma unroll 2
                for (int i = 0; i < 16; i++) {
                    int tt = (warp << 4) + i;
                    float wgt = sm.b.sc[tt];
                    float4 e0 = __ldcg(encb + (size_t)tt * 64 + lane * 2);
                    float4 e1 = __ldcg(encb + (size_t)tt * 64 + lane * 2 + 1);
                    a8[0] = fmaf(wgt, e0.x, a8[0]); a8[1] = fmaf(wgt, e0.y, a8[1]);
                    a8[2] = fmaf(wgt, e0.z, a8[2]); a8[3] = fmaf(wgt, e0.w, a8[3]);
                    a8[4] = fmaf(wgt, e1.x, a8[4]); a8[5] = fmaf(wgt, e1.y, a8[5]);
                    a8[6] = fmaf(wgt, e1.z, a8[6]); a8[7] = fmaf(wgt, e1.w, a8[7]);
                }
#pragma unroll
                for (int j = 0; j < 8; j++) sm.b.ctxp[warp][lane * 8 + j] = a8[j];
                __syncthreads();
                float cv = 0.f;
#pragma unroll
                for (int w = 0; w < 8; w++) cv += sm.b.ctxp[w][tid];
                sm.b.ctx[tid] = cv * invs;
            }
            __syncthreads();

            // LSTM epilogue (thread = d)
            float yt = sm.b.misc[2];
            int d = tid;
            float gv[4];
#pragma unroll
            for (int g = 0; g < 4; g++) {
                float a = fmaf(yt, w_ih[g * 256 + d], g_bsum[g * 256 + d]);
#pragma unroll
                for (int kq = 0; kq < 4; kq++)
                    a += __ldcg(&g_gp[(size_t)kq * (Bq * G4) + (size_t)b * G4 + g * 256 + d]);
                gv[g] = a;
            }
            float cprev = g_c[b * Dq + d];
            float cn = sigmoid_f(gv[1]) * cprev + sigmoid_f(gv[0]) * tanhf(gv[2]);
            float hn = sigmoid_f(gv[3]) * tanhf(cn);
            g_c[b * Dq + d] = cn;
            g_h[b * Dq + d] = hn;

            if (t == Tq - 1) {
                float q = hn * fcf_w[d] + sm.b.ctx[d] * fcf_w[Dq + d];
#pragma unroll
                for (int o = 16; o; o >>= 1) q += __shfl_xor_sync(0xffffffffu, q, o);
                __syncthreads();
                if (lane == 0) sm.b.red[warp] = q;
                __syncthreads();
                if (tid == 0) {
                    float tot = 0.f;
#pragma unroll
                    for (int w = 0; w < 8; w++) tot += sm.b.red[w];
                    out[b] = tot + fcf_b[0];
                }
            }
        }
        gridbar();
    }
}

__global__ void prep_kernel(const float* __restrict__ w_hh,
                            const float* __restrict__ b_ih,
                            const float* __restrict__ b_hh)
{
    int i = blockIdx.x * blockDim.x + threadIdx.x;   // 262144 threads
    if (i < G4 * Dq) {
        int j = i >> 8, k = i & 255;
        g_whhT[(size_t)k * G4 + j] = w_hh[i];
    }
    if (i < G4) g_bsum[i] = b_ih[i] + b_hh[i];
    if (i < Bq * Dq) { g_h[i] = 0.f; g_c[i] = 0.f; }
    if (i < NLEAF * 32) g_cnt[i] = 0u;
    if (i == 0) { g_master = 0u; g_gen = 0u; }
}

// encfc[b,t] = enc[b,t,:] . fc_w[0:256]   (one warp per (b,t))
__global__ void __launch_bounds__(256) encfc_kernel(
        const float* __restrict__ enc, const float* __restrict__ fc_w)
{
    int w = blockIdx.x * 8 + (threadIdx.x >> 5);   // 65536 warps
    int lane = threadIdx.x & 31;
    const float4* p = (const float4*)(enc + (size_t)w * Eq);
    const float4* q = (const float4*)fc_w;
    float s = 0.f;
#pragma unroll
    for (int j = 0; j < 2; j++) {
        float4 e = __ldcg(p + lane + 32 * j);
        float4 f = __ldg(q + lane + 32 * j);
        s += e.x * f.x + e.y * f.y + e.z * f.z + e.w * f.w;
    }
#pragma unroll
    for (int o = 16; o; o >>= 1) s += __shfl_xor_sync(0xffffffffu, s, o);
    if (lane == 0) g_encfc[w] = s;
}

__global__ void __launch_bounds__(256) pre_gemm_kernel(
        const float* __restrict__ enc, const float* __restrict__ attn_w1,
        const float* __restrict__ attn_b1)
{
    __shared__ SmA sa;
    int mt = blockIdx.x >> 2, nt = blockIdx.x & 3;   // 512 row-tiles x 4 col-tiles
    gemm128x64<__half>(&sa,
        enc + (size_t)mt * 128 * Eq, Eq,
        attn_w1 + (size_t)(2 * Dq) * Eq + nt * 64, Eq,
        g_pre + (size_t)mt * 128 * Eq + nt * 64, Eq, 256,
        attn_b1 + nt * 64);
}

extern "C" void kernel_launch(void* const* d_in, const int* in_sizes, int n_in,
                              void* d_out, int out_size)
{
    const float* enc     = (const float*)d_in[0];
    const float* yhist   = (const float*)d_in[1];
    const float* attn_w1 = (const float*)d_in[2];
    const float* attn_b1 = (const float*)d_in[3];
    const float* attn_w2 = (const float*)d_in[4];
    // d_in[5] = attn_b2: unused (softmax is shift-invariant)
    const float* w_ih    = (const float*)d_in[6];
    const float* w_hh    = (const float*)d_in[7];
    const float* b_ih    = (const float*)d_in[8];
    const float* b_hh    = (const float*)d_in[9];
    const float* fc_w    = (const float*)d_in[10];
    const float* fc_b    = (const float*)d_in[11];
    const float* fcf_w   = (const float*)d_in[12];
    const float* fcf_b   = (const float*)d_in[13];
    float* out = (float*)d_out;

    prep_kernel<<<1024, 256>>>(w_hh, b_ih, b_hh);
    encfc_kernel<<<BT / 8, 256>>>(enc, fc_w);
    pre_gemm_kernel<<<2048, 256>>>(enc, attn_w1, attn_b1);
    decoder_persist<<<NBLK, 256>>>(enc, yhist, attn_w1, attn_w2, w_ih,
                                   fc_w, fc_b, fcf_w, fcf_b, out);
}